// round 3
// baseline (speedup 1.0000x reference)
#include <cuda_runtime.h>
#include <cuda_bf16.h>
#include <cstdint>

#define BB 8
#define NN 20000
#define GG 300
#define CC 80
#define KK 4
#define MAXPOS 128

// Monotone encoding of float for unsigned atomicMax / exact-equality compare.
#define ENC_NEG1 0x407FFFFFu            // enc(-1.0f)
#define ENC_ZERO 0x80000000u            // enc(0.0f)
#define ENC_THIGH 0xBF333333u           // enc(0.7f)

__device__ __forceinline__ unsigned encf(float f) {
    unsigned u = __float_as_uint(f);
    return (u & 0x80000000u) ? ~u : (u | 0x80000000u);
}

// ---------------- device scratch (no allocations allowed) ----------------
__device__ float4   g_gt_xyxy[BB * GG];
__device__ float    g_gt_area[BB * GG];
__device__ int      g_gt_cls_start[BB * (CC + 1)];
__device__ int      g_gt_cls_list[BB * GG];
__device__ unsigned g_gt_max[BB * GG];       // encoded float max per gt row
__device__ int      g_counts[BB * GG];       // subsampled positives per gt
__device__ unsigned g_anchor_enc[BB * NN];   // encoded per-anchor max IoU
__device__ int      g_anchor_gt[BB * NN];
__device__ unsigned char g_pos[BB * NN];
__device__ int      g_bin_start[BB * CC];    // per-(b,class) segment start in arena
__device__ int      g_bin_cursor[BB * CC];   // scatter cursor (starts at bin_start)
__device__ int      g_poscnt[BB * CC];       // positives per (b, class)
__device__ int      g_bin_idx[BB * NN];      // packed per-image arenas: anchor index
__device__ float4   g_bin_box[BB * NN];      // packed per-image arenas: anchor box

// IoU: every op is an explicit *_rn intrinsic -> no FMA contraction possible,
// so inlined copies are bit-identical across all kernels (required by the
// exact-equality low-quality-match test).
__device__ __forceinline__ float iou_ga(float4 g, float garea, float4 a) {
    float hw = __fmul_rn(0.5f, a.z);
    float hh = __fmul_rn(0.5f, a.w);
    float ax1 = __fsub_rn(a.x, hw), ay1 = __fsub_rn(a.y, hh);
    float ax2 = __fadd_rn(a.x, hw), ay2 = __fadd_rn(a.y, hh);
    float aarea = __fmul_rn(__fsub_rn(ax2, ax1), __fsub_rn(ay2, ay1));
    float ltx = fmaxf(g.x, ax1), lty = fmaxf(g.y, ay1);
    float rbx = fminf(g.z, ax2), rby = fminf(g.w, ay2);
    float w = fmaxf(__fsub_rn(rbx, ltx), 0.0f);
    float h = fmaxf(__fsub_rn(rby, lty), 0.0f);
    float inter = __fmul_rn(w, h);
    float uni = __fsub_rn(__fadd_rn(garea, aarea), inter);
    return __fdiv_rn(inter, uni);
}

__device__ __forceinline__ bool better(float v1, int i1, float v2, int i2) {
    return (v1 > v2) || (v1 == v2 && i1 < i2);
}

// ---------------- K0: per-image setup (gt tables + anchor-class histogram) ----------------
__global__ void k_setup(const int* __restrict__ tgt_labels,
                        const float* __restrict__ tgt_boxes,
                        const int* __restrict__ prompt_inds) {
    int b = blockIdx.x, t = threadIdx.x;
    __shared__ int s_lab[GG];
    __shared__ int s_gcnt[CC], s_acnt[CC];
    __shared__ int s_gstart[CC + 1], s_astart[CC + 1];
    if (t < CC) { s_gcnt[t] = 0; s_acnt[t] = 0; }
    __syncthreads();
    for (int g = t; g < GG; g += 256) {
        int lab = tgt_labels[b * GG + g];
        s_lab[g] = lab;
        atomicAdd(&s_gcnt[lab], 1);
        g_counts[b * GG + g] = 0;
        g_gt_max[b * GG + g] = ENC_NEG1;
        float4 bx = ((const float4*)tgt_boxes)[b * GG + g];
        float hw = __fmul_rn(0.5f, bx.z), hh = __fmul_rn(0.5f, bx.w);
        float4 xy = make_float4(__fsub_rn(bx.x, hw), __fsub_rn(bx.y, hh),
                                __fadd_rn(bx.x, hw), __fadd_rn(bx.y, hh));
        g_gt_xyxy[b * GG + g] = xy;
        g_gt_area[b * GG + g] =
            __fmul_rn(__fsub_rn(xy.z, xy.x), __fsub_rn(xy.w, xy.y));
    }
    // anchor class histogram (coalesced, 79 iters/thread, independent loads)
#pragma unroll 4
    for (int n = t; n < NN; n += 256)
        atomicAdd(&s_acnt[prompt_inds[b * NN + n]], 1);
    __syncthreads();
    if (t == 0) {
        int ag = 0, aa = 0;
        for (int c = 0; c < CC; c++) {
            s_gstart[c] = ag; ag += s_gcnt[c];
            s_astart[c] = aa; aa += s_acnt[c];
        }
        s_gstart[CC] = ag; s_astart[CC] = aa;
    }
    __syncthreads();
    if (t <= CC) g_gt_cls_start[b * (CC + 1) + t] = s_gstart[t];
    if (t < CC) {
        g_bin_start[b * CC + t]  = s_astart[t];
        g_bin_cursor[b * CC + t] = s_astart[t];
        g_poscnt[b * CC + t] = 0;
        int pos = s_gstart[t];
        for (int g = 0; g < GG; g++)            // ascending g -> first-index tie-break
            if (s_lab[g] == t) g_gt_cls_list[b * GG + pos++] = g;
    }
}

// ---------------- K1: per-anchor max/argmax, gt_max, packed bins ----------------
__global__ void k_passA(const float* __restrict__ anchors,
                        const int* __restrict__ prompt_inds) {
    int b = blockIdx.y;
    int t = threadIdx.x;
    int n = blockIdx.x * 256 + t;
    __shared__ float4   s_box[GG];      // class-list order
    __shared__ float    s_area[GG];
    __shared__ int      s_gid[GG];
    __shared__ unsigned s_gmax[GG];     // class-list order
    __shared__ int      s_start[CC + 1];
    if (t <= CC) s_start[t] = g_gt_cls_start[b * (CC + 1) + t];
    for (int j = t; j < GG; j += 256) {
        int g = g_gt_cls_list[b * GG + j];
        s_gid[j]  = g;
        s_box[j]  = g_gt_xyxy[b * GG + g];
        s_area[j] = g_gt_area[b * GG + g];
        s_gmax[j] = ENC_NEG1;
    }
    __syncthreads();
    if (n < NN) {
        float4 a = ((const float4*)anchors)[b * NN + n];
        int cls = prompt_inds[b * NN + n];
        int s = s_start[cls], e = s_start[cls + 1];
        float best = -1.0f;
        int bestj = -1;
        for (int j = s; j < e; j++) {
            float v = iou_ga(s_box[j], s_area[j], a);
            if (v > best) { best = v; bestj = j; }
            atomicMax(&s_gmax[j], encf(v));
        }
        g_anchor_enc[b * NN + n] = encf(best);
        g_anchor_gt[b * NN + n]  = (bestj >= 0) ? s_gid[bestj] : 0;
        int p = atomicAdd(&g_bin_cursor[b * CC + cls], 1);
        g_bin_idx[b * NN + p] = n;
        g_bin_box[b * NN + p] = a;
    }
    __syncthreads();
    for (int j = t; j < GG; j += 256) {
        unsigned v = s_gmax[j];
        if (v != ENC_NEG1) atomicMax(&g_gt_max[b * GG + s_gid[j]], v);
    }
}

// ---------------- K2: positive flags + optimistic counts ----------------
// Fast path: lq positivity (enc(iou)==gt_max[g]) requires enc(am) >= gt_max[g]
// since iou <= anchor max. All gt data is served from smem.
__global__ void k_passB(const float* __restrict__ anchors,
                        const int* __restrict__ prompt_inds) {
    int b = blockIdx.y;
    int t = threadIdx.x;
    int n = blockIdx.x * 256 + t;
    __shared__ float4   s_box[GG];
    __shared__ float    s_area[GG];
    __shared__ unsigned s_gm[GG];       // finalized gt_max, class-list order
    __shared__ int      s_start[CC + 1];
    if (t <= CC) s_start[t] = g_gt_cls_start[b * (CC + 1) + t];
    for (int j = t; j < GG; j += 256) {
        int g = g_gt_cls_list[b * GG + j];
        s_box[j]  = g_gt_xyxy[b * GG + g];
        s_area[j] = g_gt_area[b * GG + g];
        s_gm[j]   = g_gt_max[b * GG + g];
    }
    __syncthreads();
    if (n >= NN) return;
    unsigned eam = g_anchor_enc[b * NN + n];
    int cls = prompt_inds[b * NN + n];
    bool pos = (eam >= ENC_THIGH);
    if (!pos && eam >= ENC_ZERO) {
        int s = s_start[cls], e = s_start[cls + 1];
        float4 a;
        bool loaded = false;
        for (int j = s; j < e; j++) {
            unsigned gm = s_gm[j];
            if (gm >= ENC_ZERO && eam >= gm) {   // necessary condition for equality
                if (!loaded) { a = ((const float4*)anchors)[b * NN + n]; loaded = true; }
                if (encf(iou_ga(s_box[j], s_area[j], a)) == gm) {
                    pos = true;
                    break;
                }
            }
        }
    }
    g_pos[b * NN + n] = pos ? 1 : 0;
    if (pos) {
        atomicAdd(&g_poscnt[b * CC + cls], 1);
        atomicAdd(&g_counts[b * GG + g_anchor_gt[b * NN + n]], 1);
    }
}

// ---------------- K3: MAX_POS fixup — one warp per (b,c), rare path ----------------
__global__ void k_fixup(const int* __restrict__ prompt_inds) {
    int w = (blockIdx.x * blockDim.x + threadIdx.x) >> 5;
    int lane = threadIdx.x & 31;
    if (w >= BB * CC) return;
    if (g_poscnt[w] <= MAXPOS) return;   // warp-uniform; common case
    int b = w / CC, c = w % CC;
    int R = 0;
    for (int base = 0; base < NN; base += 32) {      // NN % 32 == 0
        int n = base + lane;
        bool p = (prompt_inds[b * NN + n] == c) && g_pos[b * NN + n];
        unsigned m = __ballot_sync(0xffffffffu, p);
        int rank = R + __popc(m & ((1u << lane) - 1));
        if (p && rank >= MAXPOS)     // optimistically counted -> remove
            atomicSub(&g_counts[b * GG + g_anchor_gt[b * NN + n]], 1);
        R += __popc(m);
    }
}

// ---------------- K4: one warp per gt: top-4 over packed class bin + output ----------------
__global__ void k_topk(const int* __restrict__ tgt_labels,
                       float* __restrict__ out) {
    int warp = (blockIdx.x * blockDim.x + threadIdx.x) >> 5;
    int lane = threadIdx.x & 31;
    if (warp >= BB * GG) return;
    int b = warp / GG, g = warp % GG;
    const int P = BB * GG * KK;
    int count = g_counts[b * GG + g];
    int kk = min(count, KK);
    if (kk <= 0) {                                   // warp-uniform
        if (lane < KK) {
            int o = (b * GG + g) * KK + lane;
            out[o] = -1.0f;
            out[P + o] = -1.0f;
            out[2 * P + o] = 0.0f;
            out[3 * P + o] = 0.0f;
        }
        return;
    }
    int cls = tgt_labels[b * GG + g];
    float4 gt = g_gt_xyxy[b * GG + g];
    float ga = g_gt_area[b * GG + g];
    int s = g_bin_start[b * CC + cls];
    int m = g_bin_cursor[b * CC + cls] - s;

    float v[KK];
    int id[KK];
#pragma unroll
    for (int k = 0; k < KK; k++) { v[k] = -1e30f; id[k] = 0x7fffffff; }

    for (int i = lane; i < m; i += 32) {
        float4 a = g_bin_box[b * NN + s + i];        // contiguous stream
        int n = g_bin_idx[b * NN + s + i];
        float val = iou_ga(gt, ga, a);
        if (better(val, n, v[KK - 1], id[KK - 1])) {
            v[KK - 1] = val; id[KK - 1] = n;
#pragma unroll
            for (int k = KK - 2; k >= 0; k--) {
                if (better(v[k + 1], id[k + 1], v[k], id[k])) {
                    float tv = v[k]; int ti = id[k];
                    v[k] = v[k + 1]; id[k] = id[k + 1];
                    v[k + 1] = tv;  id[k + 1] = ti;
                }
            }
        }
    }

    // butterfly merge of sorted top-4 lists across the warp
#pragma unroll
    for (int off = 16; off >= 1; off >>= 1) {
        float bv[KK];
        int bi[KK];
#pragma unroll
        for (int k = 0; k < KK; k++) {
            bv[k] = __shfl_xor_sync(0xffffffffu, v[k], off);
            bi[k] = __shfl_xor_sync(0xffffffffu, id[k], off);
        }
        float rv[KK];
        int ri[KK];
        int ia = 0, ib = 0;
#pragma unroll
        for (int k = 0; k < KK; k++) {
            if (better(v[ia], id[ia], bv[ib], bi[ib])) {
                rv[k] = v[ia]; ri[k] = id[ia]; ia++;
            } else {
                rv[k] = bv[ib]; ri[k] = bi[ib]; ib++;
            }
        }
#pragma unroll
        for (int k = 0; k < KK; k++) { v[k] = rv[k]; id[k] = ri[k]; }
    }

    if (lane < KK) {
        int k = lane;
        int o = (b * GG + g) * KK + k;
        bool valid = (k < kk);
        out[o]         = valid ? (float)id[k] : -1.0f;
        out[P + o]     = valid ? (float)g    : -1.0f;
        out[2 * P + o] = valid ? 1.0f : 0.0f;
        out[3 * P + o] = valid ? v[k]  : 0.0f;
    }
}

// ---------------- launch ----------------
extern "C" void kernel_launch(void* const* d_in, const int* in_sizes, int n_in,
                              void* d_out, int out_size) {
    (void)in_sizes; (void)n_in; (void)out_size;
    const float* anchors     = (const float*)d_in[2];
    const int*   prompt_inds = (const int*)d_in[3];
    const int*   tgt_labels  = (const int*)d_in[4];
    const float* tgt_boxes   = (const float*)d_in[5];
    float* out = (float*)d_out;

    k_setup<<<BB, 256>>>(tgt_labels, tgt_boxes, prompt_inds);
    dim3 gridA((NN + 255) / 256, BB);
    k_passA<<<gridA, 256>>>(anchors, prompt_inds);
    k_passB<<<gridA, 256>>>(anchors, prompt_inds);
    k_fixup<<<(BB * CC * 32 + 255) / 256, 256>>>(prompt_inds);
    k_topk<<<(BB * GG * 32 + 255) / 256, 256>>>(tgt_labels, out);
}

// round 4
// speedup vs baseline: 1.0299x; 1.0299x over previous
#include <cuda_runtime.h>
#include <cuda_bf16.h>
#include <cstdint>

#define BB 8
#define NN 20000
#define GG 300
#define CC 80
#define KK 4
#define MAXPOS 128

// Monotone float encoding for unsigned atomicMax / exact equality.
// Sentinel for "no IoU written" is 0 (zero-init friendly); any real encoded
// IoU (iou >= 0) is >= ENC_ZERO = 0x80000000 > 0, and the passB guard
// gm >= ENC_ZERO treats 0 exactly like enc(-1).
#define ENC_ZERO 0x80000000u
#define ENC_THIGH 0xBF333333u           // enc(0.7f)

__device__ __forceinline__ unsigned encf(float f) {
    unsigned u = __float_as_uint(f);
    return (u & 0x80000000u) ? ~u : (u | 0x80000000u);
}

// ---------------- device scratch (all zero-initialized; the pipeline is a
// self-resetting state machine: K3's last block restores zeros) ----------------
__device__ float4   g_gt_xyxy[BB * GG];
__device__ float    g_gt_area[BB * GG];
__device__ int      g_gt_cls_start[BB * (CC + 1)];
__device__ int      g_gt_cls_list[BB * GG];
__device__ unsigned g_gt_max[BB * GG];       // encoded max per gt; 0 = none
__device__ int      g_counts[BB * GG];       // optimistic positives per gt
__device__ unsigned g_anchor_enc[BB * NN];   // encoded per-anchor max IoU
__device__ int      g_anchor_gt[BB * NN];
__device__ unsigned char g_pos[BB * NN];
__device__ int      g_bin_cursor[BB * CC];   // anchors per (b,class); 0 at entry
__device__ int      g_poscnt[BB * CC];       // positives per (b,class); reset in K1
__device__ int      g_bin[BB * CC * NN];     // per-(b,class) anchor index lists
__device__ unsigned g_done;                  // K3 completion counter

// IoU: every op is an explicit *_rn intrinsic -> no FMA contraction, so all
// inlined copies are bit-identical (required by the exact-equality lq test).
__device__ __forceinline__ float iou_ga(float4 g, float garea, float4 a) {
    float hw = __fmul_rn(0.5f, a.z);
    float hh = __fmul_rn(0.5f, a.w);
    float ax1 = __fsub_rn(a.x, hw), ay1 = __fsub_rn(a.y, hh);
    float ax2 = __fadd_rn(a.x, hw), ay2 = __fadd_rn(a.y, hh);
    float aarea = __fmul_rn(__fsub_rn(ax2, ax1), __fsub_rn(ay2, ay1));
    float ltx = fmaxf(g.x, ax1), lty = fmaxf(g.y, ay1);
    float rbx = fminf(g.z, ax2), rby = fminf(g.w, ay2);
    float w = fmaxf(__fsub_rn(rbx, ltx), 0.0f);
    float h = fmaxf(__fsub_rn(rby, lty), 0.0f);
    float inter = __fmul_rn(w, h);
    float uni = __fsub_rn(__fadd_rn(garea, aarea), inter);
    return __fdiv_rn(inter, uni);
}

__device__ __forceinline__ bool better(float v1, int i1, float v2, int i2) {
    return (v1 > v2) || (v1 == v2 && i1 < i2);
}

// ---------------- K1: fused setup + per-anchor max/argmax + gt_max + bins ----------------
__global__ void k_passA(const float* __restrict__ anchors,
                        const int* __restrict__ prompt_inds,
                        const int* __restrict__ tgt_labels,
                        const float* __restrict__ tgt_boxes) {
    int b = blockIdx.y;
    int t = threadIdx.x;
    int n = blockIdx.x * 256 + t;
    __shared__ float4   s_raw[GG];      // gt-order cxcywh
    __shared__ int      s_lab[GG];
    __shared__ int      s_cnt[CC];
    __shared__ int      s_start[CC + 1];
    __shared__ int      s_gid[GG];      // class-order -> gt index
    __shared__ float4   s_box[GG];      // class-order xyxy
    __shared__ float    s_area[GG];
    __shared__ unsigned s_gmax[GG];

    if (t < CC) {
        s_cnt[t] = 0;
        if (blockIdx.x == 0) g_poscnt[b * CC + t] = 0;  // safe: read only in K3
    }
    __syncthreads();
    for (int g = t; g < GG; g += 256) {
        int lab = tgt_labels[b * GG + g];
        s_lab[g] = lab;
        s_raw[g] = ((const float4*)tgt_boxes)[b * GG + g];
        atomicAdd(&s_cnt[lab], 1);
    }
    __syncthreads();
    if (t == 0) {
        int acc = 0;
        for (int c = 0; c < CC; c++) { s_start[c] = acc; acc += s_cnt[c]; }
        s_start[CC] = acc;
    }
    __syncthreads();
    if (t < CC) {                        // ascending g -> first-index tie-break
        int pos = s_start[t];
        for (int g = 0; g < GG; g++)
            if (s_lab[g] == t) s_gid[pos++] = g;
    }
    __syncthreads();
    for (int j = t; j < GG; j += 256) {
        int g = s_gid[j];
        float4 bx = s_raw[g];
        float hw = __fmul_rn(0.5f, bx.z), hh = __fmul_rn(0.5f, bx.w);
        float4 xy = make_float4(__fsub_rn(bx.x, hw), __fsub_rn(bx.y, hh),
                                __fadd_rn(bx.x, hw), __fadd_rn(bx.y, hh));
        float ar = __fmul_rn(__fsub_rn(xy.z, xy.x), __fsub_rn(xy.w, xy.y));
        s_box[j] = xy;
        s_area[j] = ar;
        s_gmax[j] = 0u;
        if (blockIdx.x == 0) {           // publish gt tables for K2/K3
            g_gt_xyxy[b * GG + g] = xy;
            g_gt_area[b * GG + g] = ar;
            g_gt_cls_list[b * GG + j] = g;
        }
    }
    if (blockIdx.x == 0 && t <= CC) g_gt_cls_start[b * (CC + 1) + t] = s_start[t];
    __syncthreads();

    if (n < NN) {
        float4 a = ((const float4*)anchors)[b * NN + n];
        int cls = prompt_inds[b * NN + n];
        int s = s_start[cls], e = s_start[cls + 1];
        float best = -1.0f;
        int bestj = -1;
        for (int j = s; j < e; j++) {
            float v = iou_ga(s_box[j], s_area[j], a);
            if (v > best) { best = v; bestj = j; }
            atomicMax(&s_gmax[j], encf(v));
        }
        g_anchor_enc[b * NN + n] = encf(best);
        g_anchor_gt[b * NN + n]  = (bestj >= 0) ? s_gid[bestj] : 0;
        int p = atomicAdd(&g_bin_cursor[b * CC + cls], 1);
        g_bin[(b * CC + cls) * NN + p] = n;
    }
    __syncthreads();
    for (int j = t; j < GG; j += 256) {
        unsigned v = s_gmax[j];
        if (v != 0u) atomicMax(&g_gt_max[b * GG + s_gid[j]], v);
    }
}

// ---------------- K2: positive flags + optimistic counts ----------------
__global__ void k_passB(const float* __restrict__ anchors,
                        const int* __restrict__ prompt_inds) {
    int b = blockIdx.y;
    int t = threadIdx.x;
    int n = blockIdx.x * 256 + t;
    __shared__ float4   s_box[GG];
    __shared__ float    s_area[GG];
    __shared__ unsigned s_gm[GG];
    __shared__ int      s_start[CC + 1];
    if (t <= CC) s_start[t] = g_gt_cls_start[b * (CC + 1) + t];
    for (int j = t; j < GG; j += 256) {
        int g = g_gt_cls_list[b * GG + j];
        s_box[j]  = g_gt_xyxy[b * GG + g];
        s_area[j] = g_gt_area[b * GG + g];
        s_gm[j]   = g_gt_max[b * GG + g];
    }
    __syncthreads();
    if (n >= NN) return;
    unsigned eam = g_anchor_enc[b * NN + n];
    int cls = prompt_inds[b * NN + n];
    bool pos = (eam >= ENC_THIGH);
    if (!pos && eam >= ENC_ZERO) {
        int s = s_start[cls], e = s_start[cls + 1];
        float4 a;
        bool loaded = false;
        for (int j = s; j < e; j++) {
            unsigned gm = s_gm[j];
            if (gm >= ENC_ZERO && eam >= gm) {  // necessary condition for equality
                if (!loaded) { a = ((const float4*)anchors)[b * NN + n]; loaded = true; }
                if (encf(iou_ga(s_box[j], s_area[j], a)) == gm) {
                    pos = true;
                    break;
                }
            }
        }
    }
    g_pos[b * NN + n] = pos ? 1 : 0;
    if (pos) {
        atomicAdd(&g_poscnt[b * CC + cls], 1);
        atomicAdd(&g_counts[b * GG + g_anchor_gt[b * NN + n]], 1);
    }
}

// ---------------- K3: per-gt top-4 (+ inline rare MAX_POS fixup) + output + reset ----------------
__global__ void k_topk(const float* __restrict__ anchors,
                       const int* __restrict__ prompt_inds,
                       const int* __restrict__ tgt_labels,
                       float* __restrict__ out) {
    int warp = (blockIdx.x * blockDim.x + threadIdx.x) >> 5;
    int lane = threadIdx.x & 31;
    const int P = BB * GG * KK;

    if (warp < BB * GG) {
        int b = warp / GG, g = warp % GG;
        int cls = tgt_labels[b * GG + g];
        int count = g_counts[b * GG + g];

        // Rare path: class exceeded MAX_POS -> deduct this gt's overflow.
        if (count > 0 && g_poscnt[b * CC + cls] > MAXPOS) {
            int R = 0, sub = 0;
            unsigned lmask = (1u << lane) - 1u;
            for (int base = 0; base < NN; base += 32) {   // NN % 32 == 0
                int n = base + lane;
                bool p = (prompt_inds[b * NN + n] == cls) && g_pos[b * NN + n];
                unsigned m = __ballot_sync(0xffffffffu, p);
                if (p && (R + __popc(m & lmask)) >= MAXPOS &&
                    g_anchor_gt[b * NN + n] == g) sub++;
                R += __popc(m);
            }
#pragma unroll
            for (int off = 16; off >= 1; off >>= 1)
                sub += __shfl_xor_sync(0xffffffffu, sub, off);
            count -= sub;
        }

        int kk = min(count, KK);
        if (kk <= 0) {
            if (lane < KK) {
                int o = (b * GG + g) * KK + lane;
                out[o] = -1.0f;
                out[P + o] = -1.0f;
                out[2 * P + o] = 0.0f;
                out[3 * P + o] = 0.0f;
            }
        } else {
            float4 gt = g_gt_xyxy[b * GG + g];
            float ga = g_gt_area[b * GG + g];
            int m = g_bin_cursor[b * CC + cls];
            const int* lst = &g_bin[(b * CC + cls) * NN];

            float v[KK];
            int id[KK];
#pragma unroll
            for (int k = 0; k < KK; k++) { v[k] = -1e30f; id[k] = 0x7fffffff; }

            for (int i = lane; i < m; i += 32) {
                int n = lst[i];
                float4 a = ((const float4*)anchors)[b * NN + n];
                float val = iou_ga(gt, ga, a);
                if (better(val, n, v[KK - 1], id[KK - 1])) {
                    v[KK - 1] = val; id[KK - 1] = n;
#pragma unroll
                    for (int k = KK - 2; k >= 0; k--) {
                        if (better(v[k + 1], id[k + 1], v[k], id[k])) {
                            float tv = v[k]; int ti = id[k];
                            v[k] = v[k + 1]; id[k] = id[k + 1];
                            v[k + 1] = tv;  id[k + 1] = ti;
                        }
                    }
                }
            }
            // butterfly merge of sorted top-4 lists across the warp
#pragma unroll
            for (int off = 16; off >= 1; off >>= 1) {
                float bv[KK];
                int bi[KK];
#pragma unroll
                for (int k = 0; k < KK; k++) {
                    bv[k] = __shfl_xor_sync(0xffffffffu, v[k], off);
                    bi[k] = __shfl_xor_sync(0xffffffffu, id[k], off);
                }
                float rv[KK];
                int ri[KK];
                int ia = 0, ib = 0;
#pragma unroll
                for (int k = 0; k < KK; k++) {
                    if (better(v[ia], id[ia], bv[ib], bi[ib])) {
                        rv[k] = v[ia]; ri[k] = id[ia]; ia++;
                    } else {
                        rv[k] = bv[ib]; ri[k] = bi[ib]; ib++;
                    }
                }
#pragma unroll
                for (int k = 0; k < KK; k++) { v[k] = rv[k]; id[k] = ri[k]; }
            }
            if (lane < KK) {
                int k = lane;
                int o = (b * GG + g) * KK + k;
                bool valid = (k < kk);
                out[o]         = valid ? (float)id[k] : -1.0f;
                out[P + o]     = valid ? (float)g    : -1.0f;
                out[2 * P + o] = valid ? 1.0f : 0.0f;
                out[3 * P + o] = valid ? v[k]  : 0.0f;
            }
        }
    }

    // ---- self-reset: last finishing block restores all scratch to zero ----
    __shared__ bool s_last;
    __threadfence();
    __syncthreads();
    if (threadIdx.x == 0) {
        unsigned d = atomicAdd(&g_done, 1u);
        s_last = (d == gridDim.x - 1);
    }
    __syncthreads();
    if (s_last) {
        int t = threadIdx.x;
        for (int i = t; i < BB * GG; i += 256) { g_counts[i] = 0; g_gt_max[i] = 0u; }
        for (int i = t; i < BB * CC; i += 256) g_bin_cursor[i] = 0;
        __threadfence();
        if (t == 0) g_done = 0u;
    }
}

// ---------------- launch ----------------
extern "C" void kernel_launch(void* const* d_in, const int* in_sizes, int n_in,
                              void* d_out, int out_size) {
    (void)in_sizes; (void)n_in; (void)out_size;
    const float* anchors     = (const float*)d_in[2];
    const int*   prompt_inds = (const int*)d_in[3];
    const int*   tgt_labels  = (const int*)d_in[4];
    const float* tgt_boxes   = (const float*)d_in[5];
    float* out = (float*)d_out;

    dim3 gridA((NN + 255) / 256, BB);
    k_passA<<<gridA, 256>>>(anchors, prompt_inds, tgt_labels, tgt_boxes);
    k_passB<<<gridA, 256>>>(anchors, prompt_inds);
    k_topk<<<(BB * GG * 32 + 255) / 256, 256>>>(anchors, prompt_inds, tgt_labels, out);
}